// round 3
// baseline (speedup 1.0000x reference)
#include <cuda_runtime.h>
#include <cstdint>

// Shapes (fixed for this problem)
//   x        [4, 2048, 4096] f32
//   eof_index[4]             i32
//   noise    [4, 8]          f32
//   A_w      [32, 4096]      f32
//   B_w      [8, 4096, 32]   f32
//   route_w  [8, 4096]       f32
//   noise_w  [8, 4096]       f32
//   out      [4, 2048, 4096] f32

#define U64 unsigned long long

// ---------------- scratch (no allocations allowed) ----------------
__device__ float g_logits[32];
__device__ float g_gates[32];
__device__ float g_At[4096 * 32];        // A transposed [k][r]
__device__ float g_Wc[4 * 4096 * 32];    // combined per-batch weight [b][o][r], scaling folded
__device__ float g_shared[4 * 2048 * 32];// shared low-rank activations [m][r], m = b*2048+s

// ---------------- packed f32x2 helpers ----------------
__device__ __forceinline__ U64 pk2(float v) {
    U64 r;
    asm("mov.b64 %0, {%1, %1};" : "=l"(r) : "f"(v));
    return r;
}
__device__ __forceinline__ void ffma2(U64 &d, U64 a, U64 b) {
    asm("fma.rn.f32x2 %0, %1, %2, %0;" : "+l"(d) : "l"(a), "l"(b));
}
__device__ __forceinline__ float2 upk(U64 v) {
    float2 r;
    asm("mov.b64 {%0, %1}, %2;" : "=f"(r.x), "=f"(r.y) : "l"(v));
    return r;
}

// ---------------- kernel 1: gating logits ----------------
// grid = 32 (one block per (b,e)), block = 256
__global__ __launch_bounds__(256) void gating_logits_kernel(
    const float* __restrict__ x, const int* __restrict__ eof,
    const float* __restrict__ noise,
    const float* __restrict__ route_w, const float* __restrict__ noise_w)
{
    int be = blockIdx.x;
    int b = be >> 3, e = be & 7;
    const float* xr = x + ((size_t)b * 2048 + (size_t)eof[b]) * 4096;
    const float* rw = route_w + e * 4096;
    const float* nw = noise_w + e * 4096;

    float c = 0.f, n = 0.f;
    int t = threadIdx.x;
    for (int k = t * 4; k < 4096; k += 256 * 4) {
        float4 xv = *(const float4*)(xr + k);
        float4 rv = *(const float4*)(rw + k);
        float4 nv = *(const float4*)(nw + k);
        c += xv.x * rv.x + xv.y * rv.y + xv.z * rv.z + xv.w * rv.w;
        n += xv.x * nv.x + xv.y * nv.y + xv.z * nv.z + xv.w * nv.w;
    }
    #pragma unroll
    for (int off = 16; off; off >>= 1) {
        c += __shfl_down_sync(0xFFFFFFFFu, c, off);
        n += __shfl_down_sync(0xFFFFFFFFu, n, off);
    }
    __shared__ float sc[8], sn[8];
    if ((t & 31) == 0) { sc[t >> 5] = c; sn[t >> 5] = n; }
    __syncthreads();
    if (t == 0) {
        float cs = 0.f, ns = 0.f;
        #pragma unroll
        for (int w = 0; w < 8; w++) { cs += sc[w]; ns += sn[w]; }
        float sp = (ns > 20.f) ? ns : log1pf(expf(ns));   // softplus
        g_logits[be] = cs + noise[b * 8 + e] * (sp + 0.01f);
    }
}

// ---------------- kernel 2: top-2 softmax -> gates ----------------
__global__ void gating_topk_kernel()
{
    int b = threadIdx.x;
    if (b < 4) {
        float v[8];
        #pragma unroll
        for (int e = 0; e < 8; e++) v[e] = g_logits[b * 8 + e];
        int i1 = 0;
        #pragma unroll
        for (int e = 1; e < 8; e++) if (v[e] > v[i1]) i1 = e;
        int i2 = (i1 == 0) ? 1 : 0;
        #pragma unroll
        for (int e = 0; e < 8; e++) if (e != i1 && v[e] > v[i2]) i2 = e;
        float e2 = expf(v[i2] - v[i1]);
        float s = 1.f + e2;
        #pragma unroll
        for (int e = 0; e < 8; e++)
            g_gates[b * 8 + e] = (e == i1) ? (1.f / s) : ((e == i2) ? (e2 / s) : 0.f);
    }
}

// ---------------- kernel 3: combine expert weights ----------------
// W_comb[b][o][r] = 2.0 * sum_e gates[b][e] * B_w[e][o][r]
// grid = 512, block = 256, one float4 per thread
__global__ __launch_bounds__(256) void combine_w_kernel(const float* __restrict__ Bw)
{
    int idx = blockIdx.x * 256 + threadIdx.x;   // float4 index, 0..131071
    int b = idx >> 15;                           // 32768 float4 per batch
    int rem4 = idx & 32767;
    float4 acc = make_float4(0.f, 0.f, 0.f, 0.f);
    #pragma unroll
    for (int e = 0; e < 8; e++) {
        float g = g_gates[b * 8 + e];
        if (g != 0.f) {
            float4 v = *(const float4*)(Bw + (size_t)e * 131072 + (size_t)rem4 * 4);
            acc.x += g * v.x; acc.y += g * v.y;
            acc.z += g * v.z; acc.w += g * v.w;
        }
    }
    acc.x *= 2.f; acc.y *= 2.f; acc.z *= 2.f; acc.w *= 2.f;  // SCALING
    *(float4*)(g_Wc + (size_t)idx * 4) = acc;
}

// ---------------- kernel 4: transpose A [32,4096] -> [4096,32] ----------------
__global__ __launch_bounds__(256) void transposeA_kernel(const float* __restrict__ Aw)
{
    int idx = blockIdx.x * 256 + threadIdx.x;   // 0..131071
    int r = idx >> 12;                          // row of A_w
    int k = idx & 4095;
    g_At[k * 32 + r] = Aw[idx];                 // coalesced read, scattered write (512KB total)
}

// ---------------- kernel 5: GEMM1  shared[m][r] = sum_k x[m][k]*A[r][k] ----------------
// M=8192, N=32, K=4096.  BM=64, BK=32, 256 threads, micro-tile 4m x 2r via f32x2.
__global__ __launch_bounds__(256) void gemm1_kernel(const float* __restrict__ x)
{
    __shared__ float Xs[32 * 66];   // [k][m], stride 66 (8B-aligned u64 loads, mild store conflicts)
    __shared__ float As[32 * 32];   // [k][r]

    int tid = threadIdx.x;
    int mbase = blockIdx.x * 64;
    int r0 = (tid & 15) * 2;
    int m0 = (tid >> 4) * 4;
    int xrow = tid >> 2;            // 0..63
    int xk   = (tid & 3) * 8;       // 0,8,16,24
    int arow = tid >> 3;            // 0..31
    int ac   = (tid & 7) * 4;

    const float* xg = x + (size_t)(mbase + xrow) * 4096 + xk;
    const float* ag = g_At + arow * 32 + ac;

    // prologue prefetch of tile 0
    float4 xa = *(const float4*)(xg);
    float4 xb = *(const float4*)(xg + 4);
    float4 av = *(const float4*)(ag);

    U64 acc00 = 0ull, acc01 = 0ull, acc10 = 0ull, acc11 = 0ull;

    for (int k0 = 0; k0 < 4096; k0 += 32) {
        __syncthreads();
        Xs[(xk + 0) * 66 + xrow] = xa.x;
        Xs[(xk + 1) * 66 + xrow] = xa.y;
        Xs[(xk + 2) * 66 + xrow] = xa.z;
        Xs[(xk + 3) * 66 + xrow] = xa.w;
        Xs[(xk + 4) * 66 + xrow] = xb.x;
        Xs[(xk + 5) * 66 + xrow] = xb.y;
        Xs[(xk + 6) * 66 + xrow] = xb.z;
        Xs[(xk + 7) * 66 + xrow] = xb.w;
        *(float4*)&As[arow * 32 + ac] = av;
        __syncthreads();

        if (k0 + 32 < 4096) {   // prefetch next tile; DRAM latency hides under compute
            xa = *(const float4*)(xg + k0 + 32);
            xb = *(const float4*)(xg + k0 + 36);
            av = *(const float4*)(ag + (size_t)(k0 + 32) * 32);
        }

        #pragma unroll
        for (int k = 0; k < 32; k++) {
            U64 s01 = *(const U64*)&Xs[k * 66 + m0];       // (m0,m1) pair direct from smem
            U64 s23 = *(const U64*)&Xs[k * 66 + m0 + 2];   // (m2,m3)
            float2 aa = *(const float2*)&As[k * 32 + r0];
            U64 a0 = pk2(aa.x);
            U64 a1 = pk2(aa.y);
            ffma2(acc00, s01, a0);
            ffma2(acc10, s23, a0);
            ffma2(acc01, s01, a1);
            ffma2(acc11, s23, a1);
        }
    }

    float2 a00 = upk(acc00), a01 = upk(acc01), a10 = upk(acc10), a11 = upk(acc11);
    float* op = g_shared + (size_t)mbase * 32;
    *(float2*)&op[(m0 + 0) * 32 + r0] = make_float2(a00.x, a01.x);
    *(float2*)&op[(m0 + 1) * 32 + r0] = make_float2(a00.y, a01.y);
    *(float2*)&op[(m0 + 2) * 32 + r0] = make_float2(a10.x, a11.x);
    *(float2*)&op[(m0 + 3) * 32 + r0] = make_float2(a10.y, a11.y);
}

// ---------------- kernel 6: GEMM2  out[b][m][o] = sum_r shared[b][m][r]*Wc[b][o][r] ----------------
// per b: M=2048, N=4096, K=32.  64x64 output tile, 256 threads, micro-tile 4m x 4o via f32x2.
__global__ __launch_bounds__(256) void gemm2_kernel(float* __restrict__ out)
{
    __shared__ float Ss[32 * 66];   // [k][m]
    __shared__ float Ws[32 * 68];   // [k][o], stride 68 keeps float4 loads 16B-aligned

    int tid = threadIdx.x;
    int b = blockIdx.z;
    int mbase = blockIdx.y * 64;
    int obase = blockIdx.x * 64;

    const float* sg = g_shared + ((size_t)b * 2048 + mbase) * 32;
    const float* wg = g_Wc + ((size_t)b * 4096 + obase) * 32;

    int row = tid >> 2;
    int kx = (tid & 3) * 8;
    float4 sa = *(const float4*)(sg + row * 32 + kx);
    float4 sb = *(const float4*)(sg + row * 32 + kx + 4);
    float4 wa = *(const float4*)(wg + row * 32 + kx);
    float4 wb = *(const float4*)(wg + row * 32 + kx + 4);

    Ss[(kx + 0) * 66 + row] = sa.x;
    Ss[(kx + 1) * 66 + row] = sa.y;
    Ss[(kx + 2) * 66 + row] = sa.z;
    Ss[(kx + 3) * 66 + row] = sa.w;
    Ss[(kx + 4) * 66 + row] = sb.x;
    Ss[(kx + 5) * 66 + row] = sb.y;
    Ss[(kx + 6) * 66 + row] = sb.z;
    Ss[(kx + 7) * 66 + row] = sb.w;
    Ws[(kx + 0) * 68 + row] = wa.x;
    Ws[(kx + 1) * 68 + row] = wa.y;
    Ws[(kx + 2) * 68 + row] = wa.z;
    Ws[(kx + 3) * 68 + row] = wa.w;
    Ws[(kx + 4) * 68 + row] = wb.x;
    Ws[(kx + 5) * 68 + row] = wb.y;
    Ws[(kx + 6) * 68 + row] = wb.z;
    Ws[(kx + 7) * 68 + row] = wb.w;
    __syncthreads();

    int o0 = (tid & 15) * 4;
    int m0 = (tid >> 4) * 4;

    U64 acc00 = 0ull, acc01 = 0ull, acc02 = 0ull, acc03 = 0ull;
    U64 acc10 = 0ull, acc11 = 0ull, acc12 = 0ull, acc13 = 0ull;

    #pragma unroll
    for (int k = 0; k < 32; k++) {
        U64 s01 = *(const U64*)&Ss[k * 66 + m0];
        U64 s23 = *(const U64*)&Ss[k * 66 + m0 + 2];
        float4 wv = *(const float4*)&Ws[k * 68 + o0];
        U64 w0 = pk2(wv.x);
        U64 w1 = pk2(wv.y);
        U64 w2 = pk2(wv.z);
        U64 w3 = pk2(wv.w);
        ffma2(acc00, s01, w0); ffma2(acc10, s23, w0);
        ffma2(acc01, s01, w1); ffma2(acc11, s23, w1);
        ffma2(acc02, s01, w2); ffma2(acc12, s23, w2);
        ffma2(acc03, s01, w3); ffma2(acc13, s23, w3);
    }

    float2 p00 = upk(acc00), p01 = upk(acc01), p02 = upk(acc02), p03 = upk(acc03);
    float2 p10 = upk(acc10), p11 = upk(acc11), p12 = upk(acc12), p13 = upk(acc13);

    float* og = out + ((size_t)(b * 2048 + mbase + m0)) * 4096 + obase + o0;
    *(float4*)(og)          = make_float4(p00.x, p01.x, p02.x, p03.x);
    *(float4*)(og + 4096)   = make_float4(p00.y, p01.y, p02.y, p03.y);
    *(float4*)(og + 8192)   = make_float4(p10.x, p11.x, p12.x, p13.x);
    *(float4*)(og + 12288)  = make_float4(p10.y, p11.y, p12.y, p13.y);
}

// ---------------- launch ----------------
extern "C" void kernel_launch(void* const* d_in, const int* in_sizes, int n_in,
                              void* d_out, int out_size)
{
    const float* x     = (const float*)d_in[0];
    const int*   eof   = (const int*)  d_in[1];
    const float* noise = (const float*)d_in[2];
    const float* Aw    = (const float*)d_in[3];
    const float* Bw    = (const float*)d_in[4];
    const float* rw    = (const float*)d_in[5];
    const float* nw    = (const float*)d_in[6];
    float* out = (float*)d_out;

    gating_logits_kernel<<<32, 256>>>(x, eof, noise, rw, nw);
    gating_topk_kernel<<<1, 32>>>();
    combine_w_kernel<<<512, 256>>>(Bw);
    transposeA_kernel<<<512, 256>>>(Aw);
    gemm1_kernel<<<128, 256>>>(x);
    gemm2_kernel<<<dim3(64, 32, 4), 256>>>(out);
}

// round 4
// speedup vs baseline: 1.2665x; 1.2665x over previous
#include <cuda_runtime.h>
#include <cstdint>

// Shapes (fixed):
//   x[4,2048,4096] f32, eof[4] i32, noise[4,8] f32, A_w[32,4096] f32,
//   B_w[8,4096,32] f32, route_w[8,4096] f32, noise_w[8,4096] f32
//   out[4,2048,4096] f32

#define U64 unsigned long long

// ---------------- scratch ----------------
__device__ float g_logits[32];
__device__ float g_At[4096 * 32];          // A transposed [k][r]
__device__ float g_Wc[4 * 4096 * 32];      // combined weight [b][o][r], 2x scaling folded
__device__ float g_part[4][8192 * 32];     // split-K partials of shared activations
__device__ float g_shared[8192 * 32];      // reduced shared activations [m][r]

// ---------------- packed f32x2 helpers ----------------
__device__ __forceinline__ U64 pk2(float v) {
    U64 r; asm("mov.b64 %0, {%1, %1};" : "=l"(r) : "f"(v)); return r;
}
__device__ __forceinline__ void ffma2(U64 &d, U64 a, U64 b) {
    asm("fma.rn.f32x2 %0, %1, %2, %0;" : "+l"(d) : "l"(a), "l"(b));
}
__device__ __forceinline__ float2 upk(U64 v) {
    float2 r; asm("mov.b64 {%0, %1}, %2;" : "=f"(r.x), "=f"(r.y) : "l"(v)); return r;
}

// ---------------- kernel 1: gating logits (32 blocks = (b,e)) ----------------
__global__ __launch_bounds__(256) void gating_logits_kernel(
    const float* __restrict__ x, const int* __restrict__ eof,
    const float* __restrict__ noise,
    const float* __restrict__ route_w, const float* __restrict__ noise_w)
{
    int be = blockIdx.x;
    int b = be >> 3, e = be & 7;
    const float* xr = x + ((size_t)b * 2048 + (size_t)eof[b]) * 4096;
    const float* rw = route_w + e * 4096;
    const float* nw = noise_w + e * 4096;

    float c = 0.f, n = 0.f;
    int t = threadIdx.x;
    for (int k = t * 4; k < 4096; k += 256 * 4) {
        float4 xv = *(const float4*)(xr + k);
        float4 rv = *(const float4*)(rw + k);
        float4 nv = *(const float4*)(nw + k);
        c += xv.x * rv.x + xv.y * rv.y + xv.z * rv.z + xv.w * rv.w;
        n += xv.x * nv.x + xv.y * nv.y + xv.z * nv.z + xv.w * nv.w;
    }
    #pragma unroll
    for (int off = 16; off; off >>= 1) {
        c += __shfl_down_sync(0xFFFFFFFFu, c, off);
        n += __shfl_down_sync(0xFFFFFFFFu, n, off);
    }
    __shared__ float sc[8], sn[8];
    if ((t & 31) == 0) { sc[t >> 5] = c; sn[t >> 5] = n; }
    __syncthreads();
    if (t == 0) {
        float cs = 0.f, ns = 0.f;
        #pragma unroll
        for (int w = 0; w < 8; w++) { cs += sc[w]; ns += sn[w]; }
        float sp = (ns > 20.f) ? ns : log1pf(expf(ns));   // softplus
        g_logits[be] = cs + noise[b * 8 + e] * (sp + 0.01f);
    }
}

// ---------------- kernel 2: combine expert weights (top-2 gates inline) --------
// W_comb[b][o][r] = 2 * (g1*B_w[i1][o][r] + g2*B_w[i2][o][r])
__global__ __launch_bounds__(256) void combine_w_kernel(const float* __restrict__ Bw)
{
    int idx = blockIdx.x * 256 + threadIdx.x;   // float4 index, 0..131071
    int b = idx >> 15;                          // 32768 float4 per batch
    int rem4 = idx & 32767;

    float v[8];
    #pragma unroll
    for (int e = 0; e < 8; e++) v[e] = g_logits[b * 8 + e];
    int i1 = 0;
    #pragma unroll
    for (int e = 1; e < 8; e++) if (v[e] > v[i1]) i1 = e;
    int i2 = (i1 == 0) ? 1 : 0;
    #pragma unroll
    for (int e = 0; e < 8; e++) if (e != i1 && v[e] > v[i2]) i2 = e;
    float e2 = expf(v[i2] - v[i1]);
    float inv = 2.f / (1.f + e2);     // SCALING folded
    float g1 = inv;
    float g2 = e2 * inv;

    float4 p = *(const float4*)(Bw + (size_t)i1 * 131072 + (size_t)rem4 * 4);
    float4 q = *(const float4*)(Bw + (size_t)i2 * 131072 + (size_t)rem4 * 4);
    float4 acc;
    acc.x = g1 * p.x + g2 * q.x;
    acc.y = g1 * p.y + g2 * q.y;
    acc.z = g1 * p.z + g2 * q.z;
    acc.w = g1 * p.w + g2 * q.w;
    *(float4*)(g_Wc + (size_t)idx * 4) = acc;
}

// ---------------- kernel 3: transpose A [32,4096] -> [4096,32] ----------------
__global__ __launch_bounds__(256) void transposeA_kernel(const float* __restrict__ Aw)
{
    int idx = blockIdx.x * 256 + threadIdx.x;   // 0..131071
    int r = idx >> 12;
    int k = idx & 4095;
    g_At[k * 32 + r] = Aw[idx];
}

// ---------------- kernel 4: GEMM1 split-K ----------------
// part[ky][m][r] = sum_{k in split ky} x[m][k]*At[k][r]
// grid = (128 m-tiles, 4 k-splits), block = 128, BM=64, BK=32, micro 4m x 4r.
__global__ __launch_bounds__(128) void gemm1_kernel(const float* __restrict__ x)
{
    __shared__ float Xs[32 * 66];   // [k][m]
    __shared__ float As[32 * 32];   // [k][r]

    int tid = threadIdx.x;
    int mbase = blockIdx.x * 64;
    int kbase = blockIdx.y * 1024;

    int xrow = tid >> 1;            // 0..63
    int xk0  = (tid & 1) * 16;      // 0 or 16
    const float* xg = x + (size_t)(mbase + xrow) * 4096 + kbase + xk0;
    const float* ag = g_At + (size_t)kbase * 32 + tid * 8;

    // prologue prefetch
    float4 x0 = *(const float4*)(xg);
    float4 x1 = *(const float4*)(xg + 4);
    float4 x2 = *(const float4*)(xg + 8);
    float4 x3 = *(const float4*)(xg + 12);
    float4 a0 = *(const float4*)(ag);
    float4 a1 = *(const float4*)(ag + 4);

    int r0 = (tid & 7) * 4;
    int m0 = (tid >> 3) * 4;

    U64 a00 = 0, a01 = 0, a02 = 0, a03 = 0;   // m-pair 0 (m0,m0+1), r0..r0+3
    U64 a10 = 0, a11 = 0, a12 = 0, a13 = 0;   // m-pair 1 (m0+2,m0+3)

    for (int t = 0; t < 32; t++) {
        __syncthreads();
        Xs[(xk0 + 0) * 66 + xrow] = x0.x;
        Xs[(xk0 + 1) * 66 + xrow] = x0.y;
        Xs[(xk0 + 2) * 66 + xrow] = x0.z;
        Xs[(xk0 + 3) * 66 + xrow] = x0.w;
        Xs[(xk0 + 4) * 66 + xrow] = x1.x;
        Xs[(xk0 + 5) * 66 + xrow] = x1.y;
        Xs[(xk0 + 6) * 66 + xrow] = x1.z;
        Xs[(xk0 + 7) * 66 + xrow] = x1.w;
        Xs[(xk0 + 8) * 66 + xrow] = x2.x;
        Xs[(xk0 + 9) * 66 + xrow] = x2.y;
        Xs[(xk0 + 10) * 66 + xrow] = x2.z;
        Xs[(xk0 + 11) * 66 + xrow] = x2.w;
        Xs[(xk0 + 12) * 66 + xrow] = x3.x;
        Xs[(xk0 + 13) * 66 + xrow] = x3.y;
        Xs[(xk0 + 14) * 66 + xrow] = x3.z;
        Xs[(xk0 + 15) * 66 + xrow] = x3.w;
        *(float4*)&As[tid * 8] = a0;
        *(float4*)&As[tid * 8 + 4] = a1;
        __syncthreads();

        if (t < 31) {
            xg += 32;
            ag += 1024;
            x0 = *(const float4*)(xg);
            x1 = *(const float4*)(xg + 4);
            x2 = *(const float4*)(xg + 8);
            x3 = *(const float4*)(xg + 12);
            a0 = *(const float4*)(ag);
            a1 = *(const float4*)(ag + 4);
        }

        #pragma unroll
        for (int k = 0; k < 32; k++) {
            U64 s01 = *(const U64*)&Xs[k * 66 + m0];
            U64 s23 = *(const U64*)&Xs[k * 66 + m0 + 2];
            float4 av = *(const float4*)&As[k * 32 + r0];
            U64 b0 = pk2(av.x), b1 = pk2(av.y), b2 = pk2(av.z), b3 = pk2(av.w);
            ffma2(a00, s01, b0); ffma2(a10, s23, b0);
            ffma2(a01, s01, b1); ffma2(a11, s23, b1);
            ffma2(a02, s01, b2); ffma2(a12, s23, b2);
            ffma2(a03, s01, b3); ffma2(a13, s23, b3);
        }
    }

    float2 u00 = upk(a00), u01 = upk(a01), u02 = upk(a02), u03 = upk(a03);
    float2 u10 = upk(a10), u11 = upk(a11), u12 = upk(a12), u13 = upk(a13);
    float* op = g_part[blockIdx.y] + (size_t)(mbase + m0) * 32 + r0;
    *(float4*)(op)          = make_float4(u00.x, u01.x, u02.x, u03.x);
    *(float4*)(op + 32)     = make_float4(u00.y, u01.y, u02.y, u03.y);
    *(float4*)(op + 64)     = make_float4(u10.x, u11.x, u12.x, u13.x);
    *(float4*)(op + 96)     = make_float4(u10.y, u11.y, u12.y, u13.y);
}

// ---------------- kernel 5: reduce split-K partials ----------------
__global__ __launch_bounds__(256) void reduce_shared_kernel()
{
    int idx = blockIdx.x * 256 + threadIdx.x;   // float4 idx, 0..65535
    float4 a = *(const float4*)(g_part[0] + (size_t)idx * 4);
    float4 b = *(const float4*)(g_part[1] + (size_t)idx * 4);
    float4 c = *(const float4*)(g_part[2] + (size_t)idx * 4);
    float4 d = *(const float4*)(g_part[3] + (size_t)idx * 4);
    float4 s;
    s.x = (a.x + b.x) + (c.x + d.x);
    s.y = (a.y + b.y) + (c.y + d.y);
    s.z = (a.z + b.z) + (c.z + d.z);
    s.w = (a.w + b.w) + (c.w + d.w);
    *(float4*)(g_shared + (size_t)idx * 4) = s;
}

// ---------------- kernel 6: GEMM2 ----------------
// out[b][m][o] = sum_r shared[b*2048+m][r] * Wc[b][o][r]
// tile 128m x 64o, K=32, 256 threads, micro 8m x 4o.
__global__ __launch_bounds__(256) void gemm2_kernel(float* __restrict__ out)
{
    __shared__ float Ss[32 * 130];  // [k][m]
    __shared__ float Ws[32 * 68];   // [k][o]

    int tid = threadIdx.x;
    int b = blockIdx.z;
    int mbase = blockIdx.y * 128;
    int obase = blockIdx.x * 64;

    const float* sg = g_shared + ((size_t)b * 2048 + mbase) * 32;
    const float* wg = g_Wc + ((size_t)b * 4096 + obase) * 32;

    // load S: 128 rows x 32 k -> Ss[k][m]
    {
        int row = tid >> 1;            // 0..127
        int k0 = (tid & 1) * 16;
        const float* p = sg + row * 32 + k0;
        float4 s0 = *(const float4*)(p);
        float4 s1 = *(const float4*)(p + 4);
        float4 s2 = *(const float4*)(p + 8);
        float4 s3 = *(const float4*)(p + 12);
        Ss[(k0 + 0) * 130 + row] = s0.x;
        Ss[(k0 + 1) * 130 + row] = s0.y;
        Ss[(k0 + 2) * 130 + row] = s0.z;
        Ss[(k0 + 3) * 130 + row] = s0.w;
        Ss[(k0 + 4) * 130 + row] = s1.x;
        Ss[(k0 + 5) * 130 + row] = s1.y;
        Ss[(k0 + 6) * 130 + row] = s1.z;
        Ss[(k0 + 7) * 130 + row] = s1.w;
        Ss[(k0 + 8) * 130 + row] = s2.x;
        Ss[(k0 + 9) * 130 + row] = s2.y;
        Ss[(k0 + 10) * 130 + row] = s2.z;
        Ss[(k0 + 11) * 130 + row] = s2.w;
        Ss[(k0 + 12) * 130 + row] = s3.x;
        Ss[(k0 + 13) * 130 + row] = s3.y;
        Ss[(k0 + 14) * 130 + row] = s3.z;
        Ss[(k0 + 15) * 130 + row] = s3.w;
    }
    // load W: 64 rows x 32 k -> Ws[k][o]
    {
        int row = tid >> 2;            // 0..63
        int k0 = (tid & 3) * 8;
        const float* p = wg + row * 32 + k0;
        float4 w0 = *(const float4*)(p);
        float4 w1 = *(const float4*)(p + 4);
        Ws[(k0 + 0) * 68 + row] = w0.x;
        Ws[(k0 + 1) * 68 + row] = w0.y;
        Ws[(k0 + 2) * 68 + row] = w0.z;
        Ws[(k0 + 3) * 68 + row] = w0.w;
        Ws[(k0 + 4) * 68 + row] = w1.x;
        Ws[(k0 + 5) * 68 + row] = w1.y;
        Ws[(k0 + 6) * 68 + row] = w1.z;
        Ws[(k0 + 7) * 68 + row] = w1.w;
    }
    __syncthreads();

    int o0 = (tid & 15) * 4;
    int m0 = (tid >> 4) * 8;

    U64 a00 = 0, a01 = 0, a02 = 0, a03 = 0;   // m-pair (m0,m0+1)
    U64 a10 = 0, a11 = 0, a12 = 0, a13 = 0;   // (m0+2,m0+3)
    U64 a20 = 0, a21 = 0, a22 = 0, a23 = 0;   // (m0+4,m0+5)
    U64 a30 = 0, a31 = 0, a32 = 0, a33 = 0;   // (m0+6,m0+7)

    #pragma unroll
    for (int k = 0; k < 32; k++) {
        U64 s01 = *(const U64*)&Ss[k * 130 + m0];
        U64 s23 = *(const U64*)&Ss[k * 130 + m0 + 2];
        U64 s45 = *(const U64*)&Ss[k * 130 + m0 + 4];
        U64 s67 = *(const U64*)&Ss[k * 130 + m0 + 6];
        float4 wv = *(const float4*)&Ws[k * 68 + o0];
        U64 w0 = pk2(wv.x), w1 = pk2(wv.y), w2 = pk2(wv.z), w3 = pk2(wv.w);
        ffma2(a00, s01, w0); ffma2(a10, s23, w0); ffma2(a20, s45, w0); ffma2(a30, s67, w0);
        ffma2(a01, s01, w1); ffma2(a11, s23, w1); ffma2(a21, s45, w1); ffma2(a31, s67, w1);
        ffma2(a02, s01, w2); ffma2(a12, s23, w2); ffma2(a22, s45, w2); ffma2(a32, s67, w2);
        ffma2(a03, s01, w3); ffma2(a13, s23, w3); ffma2(a23, s45, w3); ffma2(a33, s67, w3);
    }

    float* og = out + ((size_t)(b * 2048 + mbase + m0)) * 4096 + obase + o0;
    {
        float2 p0 = upk(a00), p1 = upk(a01), p2 = upk(a02), p3 = upk(a03);
        *(float4*)(og)        = make_float4(p0.x, p1.x, p2.x, p3.x);
        *(float4*)(og + 4096) = make_float4(p0.y, p1.y, p2.y, p3.y);
    }
    {
        float2 p0 = upk(a10), p1 = upk(a11), p2 = upk(a12), p3 = upk(a13);
        *(float4*)(og + 2 * 4096) = make_float4(p0.x, p1.x, p2.x, p3.x);
        *(float4*)(og + 3 * 4096) = make_float4(p0.y, p1.y, p2.y, p3.y);
    }
    {
        float2 p0 = upk(a20), p1 = upk(a21), p2 = upk(a22), p3 = upk(a23);
        *(float4*)(og + 4 * 4096) = make_float4(p0.x, p1.x, p2.x, p3.x);
        *(float4*)(og + 5 * 4096) = make_float4(p0.y, p1.y, p2.y, p3.y);
    }
    {
        float2 p0 = upk(a30), p1 = upk(a31), p2 = upk(a32), p3 = upk(a33);
        *(float4*)(og + 6 * 4096) = make_float4(p0.x, p1.x, p2.x, p3.x);
        *(float4*)(og + 7 * 4096) = make_float4(p0.y, p1.y, p2.y, p3.y);
    }
}

// ---------------- launch ----------------
extern "C" void kernel_launch(void* const* d_in, const int* in_sizes, int n_in,
                              void* d_out, int out_size)
{
    const float* x     = (const float*)d_in[0];
    const int*   eof   = (const int*)  d_in[1];
    const float* noise = (const float*)d_in[2];
    const float* Aw    = (const float*)d_in[3];
    const float* Bw    = (const float*)d_in[4];
    const float* rw    = (const float*)d_in[5];
    const float* nw    = (const float*)d_in[6];
    float* out = (float*)d_out;

    gating_logits_kernel<<<32, 256>>>(x, eof, noise, rw, nw);
    transposeA_kernel<<<512, 256>>>(Aw);
    combine_w_kernel<<<512, 256>>>(Bw);
    gemm1_kernel<<<dim3(128, 4), 128>>>(x);
    reduce_shared_kernel<<<256, 256>>>();
    gemm2_kernel<<<dim3(64, 16, 4), 256>>>(out);
}